// round 2
// baseline (speedup 1.0000x reference)
#include <cuda_runtime.h>

#define ALPHA_F 0.25f
#define CRIT_PEN 50.0

// accumulators: [0]=sum(w*ce) [1]=sum(w) [2]=sum(focal) [3]=sum(penalty)
//               [4]=n_crit    [5]=n_miss
__device__ double g_acc[6];

__global__ void acsl_init_kernel() {
    if (threadIdx.x < 6) g_acc[threadIdx.x] = 0.0;
}

__device__ __forceinline__ void acsl_sample(
    float o0, float o1, float o2, int tt_raw,
    const float* s_cw, const float* s_pm,
    float& a_wce, float& a_w, float& a_focal, float& a_pen,
    int& a_crit, int& a_miss)
{
    int tt = min(max(tt_raw, 0), 2);   // defensive: never index OOB

    float m  = fmaxf(o0, fmaxf(o1, o2));
    float e0 = __expf(o0 - m);
    float e1 = __expf(o1 - m);
    float e2 = __expf(o2 - m);
    float S  = e0 + e1 + e2;

    float ot = (tt == 0) ? o0 : ((tt == 1) ? o1 : o2);
    float et = (tt == 0) ? e0 : ((tt == 1) ? e1 : e2);

    float ce = __logf(S) - (ot - m);
    float pt = __fdividef(et, S);          // == exp(-ce)
    float omp = 1.0f - pt;
    float focal = ALPHA_F * omp * omp * ce;

    // argmax, first-max tie-break (matches jnp.argmax)
    int pred = 0; float best = o0;
    if (o1 > best) { best = o1; pred = 1; }
    if (o2 > best) { best = o2; pred = 2; }

    float w = s_cw[tt];
    a_wce   += w * ce;
    a_w     += w;
    a_focal += focal;
    a_pen   += s_pm[tt * 3 + pred];
    int is_crit = (tt == 2);
    a_crit  += is_crit;
    a_miss  += is_crit & (pred != 2);
}

__global__ __launch_bounds__(256)
void acsl_main_kernel(const float* __restrict__ outputs,
                      const int* __restrict__ targets,
                      const float* __restrict__ cw,
                      const float* __restrict__ pm,
                      int nvec, int B)
{
    __shared__ float s_cw[3];
    __shared__ float s_pm[9];
    __shared__ double s_part[6][8];

    int tid = threadIdx.x;
    if (tid < 3) s_cw[tid] = cw[tid];
    if (tid < 9) s_pm[tid] = pm[tid];
    __syncthreads();

    float a_wce = 0.f, a_w = 0.f, a_focal = 0.f, a_pen = 0.f;
    int a_crit = 0, a_miss = 0;

    const float4* out4 = (const float4*)outputs;
    const int4*   tgt4 = (const int4*)targets;

    int gthreads = gridDim.x * blockDim.x;
    int g = blockIdx.x * blockDim.x + tid;

    for (int v = g; v < nvec; v += gthreads) {
        float4 f0 = out4[3 * v + 0];
        float4 f1 = out4[3 * v + 1];
        float4 f2 = out4[3 * v + 2];
        int4   t  = tgt4[v];

        acsl_sample(f0.x, f0.y, f0.z, t.x, s_cw, s_pm,
                    a_wce, a_w, a_focal, a_pen, a_crit, a_miss);
        acsl_sample(f0.w, f1.x, f1.y, t.y, s_cw, s_pm,
                    a_wce, a_w, a_focal, a_pen, a_crit, a_miss);
        acsl_sample(f1.z, f1.w, f2.x, t.z, s_cw, s_pm,
                    a_wce, a_w, a_focal, a_pen, a_crit, a_miss);
        acsl_sample(f2.y, f2.z, f2.w, t.w, s_cw, s_pm,
                    a_wce, a_w, a_focal, a_pen, a_crit, a_miss);
    }

    // scalar tail (B not divisible by 4)
    int tail_start = nvec * 4;
    for (int i = tail_start + g; i < B; i += gthreads) {
        float o0 = outputs[3 * i + 0];
        float o1 = outputs[3 * i + 1];
        float o2 = outputs[3 * i + 2];
        acsl_sample(o0, o1, o2, targets[i], s_cw, s_pm,
                    a_wce, a_w, a_focal, a_pen, a_crit, a_miss);
    }

    // warp reduction (float/int partials)
    #pragma unroll
    for (int off = 16; off > 0; off >>= 1) {
        a_wce   += __shfl_xor_sync(0xffffffffu, a_wce,   off);
        a_w     += __shfl_xor_sync(0xffffffffu, a_w,     off);
        a_focal += __shfl_xor_sync(0xffffffffu, a_focal, off);
        a_pen   += __shfl_xor_sync(0xffffffffu, a_pen,   off);
        a_crit  += __shfl_xor_sync(0xffffffffu, a_crit,  off);
        a_miss  += __shfl_xor_sync(0xffffffffu, a_miss,  off);
    }

    int wid = tid >> 5;
    int lid = tid & 31;
    if (lid == 0) {
        s_part[0][wid] = (double)a_wce;
        s_part[1][wid] = (double)a_w;
        s_part[2][wid] = (double)a_focal;
        s_part[3][wid] = (double)a_pen;
        s_part[4][wid] = (double)a_crit;
        s_part[5][wid] = (double)a_miss;
    }
    __syncthreads();

    // first 6 threads each reduce one accumulator over 8 warps -> 1 RED each
    if (tid < 6) {
        double s = 0.0;
        #pragma unroll
        for (int w = 0; w < 8; w++) s += s_part[tid][w];
        atomicAdd(&g_acc[tid], s);
    }
}

__global__ void acsl_finalize_kernel(float* __restrict__ out, double invB) {
    double ce_loss = g_acc[0] / g_acc[1];
    double focal   = g_acc[2] * invB;
    double pen     = g_acc[3] * invB;
    double n_crit  = g_acc[4];
    double miss    = g_acc[5];
    double crit = (n_crit > 0.0) ? (miss / fmax(n_crit, 1.0)) * CRIT_PEN : 0.0;
    out[0] = (float)(ce_loss + 0.3 * focal + 0.4 * pen + 0.6 * crit);
}

extern "C" void kernel_launch(void* const* d_in, const int* in_sizes, int n_in,
                              void* d_out, int out_size)
{
    const float* outputs = (const float*)d_in[0];
    const int*   targets = (const int*)d_in[1];
    const float* cw      = (const float*)d_in[2];
    const float* pm      = (const float*)d_in[3];
    float* out = (float*)d_out;

    int B = in_sizes[1];          // number of samples (targets count)
    int nvec = B / 4;

    acsl_init_kernel<<<1, 32>>>();

    int threads = 256;
    int blocks = (nvec + threads - 1) / threads;
    if (blocks > 2048) blocks = 2048;
    if (blocks < 1) blocks = 1;
    acsl_main_kernel<<<blocks, threads>>>(outputs, targets, cw, pm, nvec, B);

    acsl_finalize_kernel<<<1, 1>>>(out, 1.0 / (double)B);
}